// round 14
// baseline (speedup 1.0000x reference)
#include <cuda_runtime.h>
#include <cuda_fp16.h>
#include <cstdint>

// Problem dims
#define DD 2048
#define HH 1408
#define EE 8
#define TT 4096
#define CAP 4096
#define WELEMS (EE * HH * DD)

#define BK 64                     // halfs per stage (128B rows)
#define NS1 (DD / BK)             // 32
#define NS2 (HH / BK)             // 22
#define STAGE_B 32768             // 256 rows x 128 bytes
#define OFF_B 16384               // B region byte offset within stage
#define SMEM_DYN (512 + 3 * STAGE_B)   // 98816 -> 2 CTAs/SM
#define GATE_SMEM (EE * DD * 4)        // 65536

// ---- global scratch (no allocs allowed) ----
__device__ int    g_count[EE];
__device__ int    g_tokens[EE * CAP];   // expert slot -> token
__device__ int    g_tidx[TT * 2];       // token -> expert
__device__ int    g_pos[TT * 2];        // token -> slot within expert
__device__ float  g_tw[TT * 2];         // token -> combine weight
__device__ __half g_W1h[WELEMS];
__device__ __half g_W3h[WELEMS];
__device__ __half g_W2h[WELEMS];
__device__ __half g_xh[(size_t)TT * DD];
__device__ __half g_Gh[(size_t)EE * CAP * HH];
__device__ __half g_Yh[(size_t)EE * CAP * DD];  // unweighted expert outputs

// ---------------------------------------------------------------------------
__device__ __forceinline__ uint32_t smem_u32(const void* p) {
    uint32_t a;
    asm("{ .reg .u64 t; cvta.to.shared.u64 t, %1; cvt.u32.u64 %0, t; }" : "=r"(a) : "l"(p));
    return a;
}
#define CP16(dst, src) \
    asm volatile("cp.async.cg.shared.global [%0], [%1], 16;" :: "r"(dst), "l"(src) : "memory")
#define CP_COMMIT() asm volatile("cp.async.commit_group;" ::: "memory")
#define CP_WAIT1()  asm volatile("cp.async.wait_group 1;" ::: "memory")

// XOR-swizzled byte offset within a 128B-row tile region
__device__ __forceinline__ uint32_t swadr(int row, int chunk, int tg) {
    return (uint32_t)(row * 128 + ((chunk ^ (row & 7)) << 4) + tg * 4);
}

__device__ __forceinline__ void ldsm_x4(uint32_t& r0, uint32_t& r1,
                                        uint32_t& r2, uint32_t& r3, uint32_t addr) {
    asm volatile("ldmatrix.sync.aligned.m8n8.x4.shared.b16 {%0,%1,%2,%3}, [%4];"
                 : "=r"(r0), "=r"(r1), "=r"(r2), "=r"(r3) : "r"(addr));
}

__device__ __forceinline__ void mma_f16(float* c, const uint32_t* a,
                                        uint32_t b0, uint32_t b1) {
    asm volatile(
        "mma.sync.aligned.m16n8k16.row.col.f32.f16.f16.f32 "
        "{%0,%1,%2,%3},{%4,%5,%6,%7},{%8,%9},{%0,%1,%2,%3};"
        : "+f"(c[0]), "+f"(c[1]), "+f"(c[2]), "+f"(c[3])
        : "r"(a[0]), "r"(a[1]), "r"(a[2]), "r"(a[3]), "r"(b0), "r"(b1));
}
__device__ __forceinline__ float silu_f(float v) { return v / (1.0f + expf(-v)); }

// ---------------------------------------------------------------------------
__global__ void k_init() {
    int i = blockIdx.x * blockDim.x + threadIdx.x;
    if (i < EE * CAP) g_tokens[i] = 0;
    if (i < EE) g_count[i] = 0;
}

// streaming fp32 -> fp16 weight conversion (blockIdx.y selects tensor)
__global__ void __launch_bounds__(256) k_convert(const float* __restrict__ W1,
                                                 const float* __restrict__ W3,
                                                 const float* __restrict__ W2) {
    size_t i = ((size_t)blockIdx.x * blockDim.x + threadIdx.x) * 4;
    if (i >= WELEMS) return;
    const float* src;
    __half* dst;
    if (blockIdx.y == 0)      { src = W1; dst = g_W1h; }
    else if (blockIdx.y == 1) { src = W3; dst = g_W3h; }
    else                      { src = W2; dst = g_W2h; }
    float4 v = *(const float4*)(src + i);
    *(__half2*)(dst + i)     = __floats2half2_rn(v.x, v.y);
    *(__half2*)(dst + i + 2) = __floats2half2_rn(v.z, v.w);
}

// gating + routing fused: Wg staged in SMEM once per block (8 tokens/block,
// one warp per token). Writes x_h (fp16 copy); lane 0 routes via atomics.
__global__ void __launch_bounds__(256) k_gate(const float* __restrict__ x,
                                              const float* __restrict__ Wg) {
    extern __shared__ __align__(16) float swg[];   // [EE * DD]
    int tid = threadIdx.x;
    for (int i = tid; i < EE * DD / 4; i += 256)
        ((float4*)swg)[i] = ((const float4*)Wg)[i];
    __syncthreads();

    int warp = tid >> 5, lane = tid & 31;
    int t = blockIdx.x * 8 + warp;
    float a[EE];
#pragma unroll
    for (int e = 0; e < EE; e++) a[e] = 0.0f;
    const float4* xr = (const float4*)(x + (size_t)t * DD);
    const float4* wg = (const float4*)swg;
    __half2* xh = (__half2*)(g_xh + (size_t)t * DD);
#pragma unroll 4
    for (int k = lane; k < DD / 4; k += 32) {
        float4 xv = xr[k];
        xh[2 * k]     = __floats2half2_rn(xv.x, xv.y);
        xh[2 * k + 1] = __floats2half2_rn(xv.z, xv.w);
#pragma unroll
        for (int e = 0; e < EE; e++) {
            float4 wv = wg[e * (DD / 4) + k];
            a[e] += xv.x * wv.x + xv.y * wv.y + xv.z * wv.z + xv.w * wv.w;
        }
    }
#pragma unroll
    for (int off = 16; off; off >>= 1) {
#pragma unroll
        for (int e = 0; e < EE; e++) a[e] += __shfl_xor_sync(0xffffffffu, a[e], off);
    }
    if (lane == 0) {
        float m = a[0];
#pragma unroll
        for (int e = 1; e < EE; e++) m = fmaxf(m, a[e]);
        float s = 0.0f;
#pragma unroll
        for (int e = 0; e < EE; e++) s += expf(a[e] - m);
        int i1 = 0;
#pragma unroll
        for (int e = 1; e < EE; e++) if (a[e] > a[i1]) i1 = e;
        int i2 = (i1 == 0) ? 1 : 0;
#pragma unroll
        for (int e = 0; e < EE; e++) if (e != i1 && a[e] > a[i2]) i2 = e;
        int p1 = atomicAdd(&g_count[i1], 1);
        int p2 = atomicAdd(&g_count[i2], 1);
        g_tokens[i1 * CAP + p1] = t;
        g_tokens[i2 * CAP + p2] = t;
        g_tidx[t * 2 + 0] = i1; g_pos[t * 2 + 0] = p1;
        g_tw[t * 2 + 0] = expf(a[i1] - m) / s;
        g_tidx[t * 2 + 1] = i2; g_pos[t * 2 + 1] = p2;
        g_tw[t * 2 + 1] = expf(a[i2] - m) / s;
    }
}

// ---------------------------------------------------------------------------
// gemm1: block 128M x 128N fp16 HMMA.16816, 4 warps 2x2, warp tile 64x64,
// BK=64, XOR-swizzled SMEM, 3-stage cp.async, ldmatrix fragment loads,
// 2 CTAs/SM. B rows interleave W1/W3 in 32-row groups -> silu warp-local.
// ---------------------------------------------------------------------------
__global__ void __launch_bounds__(128, 2) k_gemm1() {
    int e = blockIdx.z;
    int cnt = g_count[e];
    int m0 = blockIdx.x * 128;
    if (m0 >= cnt) return;
    int n0 = blockIdx.y * 64;   // 64 H-columns per block

    extern __shared__ __align__(16) char smem[];
    int* srow = (int*)smem;
    uint32_t sb = smem_u32(smem);
    int tid = threadIdx.x, w = tid >> 5, lane = tid & 31, tg = lane & 3;
    int wm = w >> 1, wn = w & 1;

    srow[tid] = g_tokens[e * CAP + m0 + tid] * DD;
    __syncthreads();

    // ldmatrix per-lane address components
    uint32_t perA[4], xorA[4];
    int cA = (lane >> 4) & 1;            // chunk offset (matrices 2,3)
#pragma unroll
    for (int mi = 0; mi < 4; mi++) {
        int rowA = wm * 64 + mi * 16 + (lane & 7) + ((lane >> 3) & 1) * 8;
        perA[mi] = (uint32_t)(rowA * 128);
        xorA[mi] = (uint32_t)(rowA & 7);
    }
    uint32_t perB[4], xorB[4];
    int cB = (lane >> 3) & 1;            // chunk offset (matrices 1,3)
#pragma unroll
    for (int bi = 0; bi < 4; bi++) {
        int rowB = wn * 64 + (2 * bi + ((lane >> 4) & 1)) * 8 + (lane & 7);
        perB[bi] = (uint32_t)(rowB * 128);
        xorB[bi] = (uint32_t)(rowB & 7);
    }

    const __half* w1b = g_W1h + ((size_t)e * HH + n0) * DD;
    const __half* w3b = g_W3h + ((size_t)e * HH + n0) * DD;

    auto issue = [&](int s) {
        if (s < NS1) {
            int k0 = s * BK;
            uint32_t bs = sb + 512 + (s % 3) * STAGE_B;
#pragma unroll
            for (int i = 0; i < 8; i++) {
                int u = tid + i * 128, row = u >> 3, c8 = u & 7;
                CP16(bs + swadr(row, c8, 0), g_xh + srow[row] + k0 + c8 * 8);
            }
#pragma unroll
            for (int i = 0; i < 8; i++) {
                int u = tid + i * 128, row = u >> 3, c8 = u & 7;
                int colh = (row >> 6) * 32 + (row & 31);
                const __half* src = ((row & 32) ? w3b : w1b) + (size_t)colh * DD;
                CP16(bs + OFF_B + swadr(row, c8, 0), src + k0 + c8 * 8);
            }
        }
        CP_COMMIT();
    };

    float acc[4][8][4];
#pragma unroll
    for (int mi = 0; mi < 4; mi++)
#pragma unroll
        for (int ni = 0; ni < 8; ni++)
#pragma unroll
            for (int q = 0; q < 4; q++) acc[mi][ni][q] = 0.0f;

    issue(0);
    issue(1);
    for (int s = 0; s < NS1; s++) {
        CP_WAIT1();
        __syncthreads();
        issue(s + 2);
        uint32_t stA = sb + 512 + (s % 3) * STAGE_B;
        uint32_t stB = stA + OFF_B;
#pragma unroll
        for (int ks = 0; ks < 64; ks += 16) {
            uint32_t ck = (uint32_t)(ks >> 3);
            uint32_t a[4][4], b[4][4];
#pragma unroll
            for (int mi = 0; mi < 4; mi++)
                ldsm_x4(a[mi][0], a[mi][1], a[mi][2], a[mi][3],
                        stA + perA[mi] + (((ck + cA) ^ xorA[mi]) << 4));
#pragma unroll
            for (int bi = 0; bi < 4; bi++)
                ldsm_x4(b[bi][0], b[bi][1], b[bi][2], b[bi][3],
                        stB + perB[bi] + (((ck + cB) ^ xorB[bi]) << 4));
#pragma unroll
            for (int ni = 0; ni < 8; ni++) {
                uint32_t b0 = b[ni >> 1][(ni & 1) * 2];
                uint32_t b1 = b[ni >> 1][(ni & 1) * 2 + 1];
#pragma unroll
                for (int mi = 0; mi < 4; mi++)
                    mma_f16(acc[mi][ni], a[mi], b0, b1);
            }
        }
    }

    // epilogue: silu pairing warp-local; store G as fp16
    int gr = lane >> 2;
#pragma unroll
    for (int mi = 0; mi < 4; mi++) {
        int r = m0 + wm * 64 + mi * 16 + gr;
        __half* gp = g_Gh + ((size_t)e * CAP + r) * HH + n0 + wn * 32;
#pragma unroll
        for (int ni = 0; ni < 4; ni++) {
            int c = ni * 8 + tg * 2;
            float g0 = silu_f(acc[mi][ni][0]) * acc[mi][ni + 4][0];
            float g1 = silu_f(acc[mi][ni][1]) * acc[mi][ni + 4][1];
            float g2 = silu_f(acc[mi][ni][2]) * acc[mi][ni + 4][2];
            float g3 = silu_f(acc[mi][ni][3]) * acc[mi][ni + 4][3];
            *(__half2*)(gp + c) = __floats2half2_rn(g0, g1);
            *(__half2*)(gp + (size_t)8 * HH + c) = __floats2half2_rn(g2, g3);
        }
    }
}

// ---------------------------------------------------------------------------
// gemm2: block 128M x 128N (d-cols), fp16 HMMA + ldmatrix, K over H;
// stores unweighted expert outputs as fp16 into g_Yh (no atomics).
// ---------------------------------------------------------------------------
__global__ void __launch_bounds__(128, 2) k_gemm2() {
    int e = blockIdx.z;
    int cnt = g_count[e];
    int m0 = blockIdx.x * 128;
    if (m0 >= cnt) return;
    int n0 = blockIdx.y * 128;

    extern __shared__ __align__(16) char smem[];
    uint32_t sb = smem_u32(smem);
    int tid = threadIdx.x, w = tid >> 5, lane = tid & 31, tg = lane & 3;
    int wm = w >> 1, wn = w & 1;

    uint32_t perA[4], xorA[4];
    int cA = (lane >> 4) & 1;
#pragma unroll
    for (int mi = 0; mi < 4; mi++) {
        int rowA = wm * 64 + mi * 16 + (lane & 7) + ((lane >> 3) & 1) * 8;
        perA[mi] = (uint32_t)(rowA * 128);
        xorA[mi] = (uint32_t)(rowA & 7);
    }
    uint32_t perB[4], xorB[4];
    int cB = (lane >> 3) & 1;
#pragma unroll
    for (int bi = 0; bi < 4; bi++) {
        int rowB = wn * 64 + (2 * bi + ((lane >> 4) & 1)) * 8 + (lane & 7);
        perB[bi] = (uint32_t)(rowB * 128);
        xorB[bi] = (uint32_t)(rowB & 7);
    }

    const __half* ab  = g_Gh + ((size_t)e * CAP + m0) * HH;
    const __half* w2b = g_W2h + ((size_t)e * DD + n0) * HH;

    auto issue = [&](int s) {
        if (s < NS2) {
            int k0 = s * BK;
            uint32_t bs = sb + 512 + (s % 3) * STAGE_B;
#pragma unroll
            for (int i = 0; i < 8; i++) {
                int u = tid + i * 128, row = u >> 3, c8 = u & 7;
                CP16(bs + swadr(row, c8, 0), ab + (size_t)row * HH + k0 + c8 * 8);
            }
#pragma unroll
            for (int i = 0; i < 8; i++) {
                int u = tid + i * 128, row = u >> 3, c8 = u & 7;
                CP16(bs + OFF_B + swadr(row, c8, 0), w2b + (size_t)row * HH + k0 + c8 * 8);
            }
        }
        CP_COMMIT();
    };

    float acc[4][8][4];
#pragma unroll
    for (int mi = 0; mi < 4; mi++)
#pragma unroll
        for (int ni = 0; ni < 8; ni++)
#pragma unroll
            for (int q = 0; q < 4; q++) acc[mi][ni][q] = 0.0f;

    issue(0);
    issue(1);
    for (int s = 0; s < NS2; s++) {
        CP_WAIT1();
        __syncthreads();
        issue(s + 2);
        uint32_t stA = sb + 512 + (s % 3) * STAGE_B;
        uint32_t stB = stA + OFF_B;
#pragma unroll
        for (int ks = 0; ks < 64; ks += 16) {
            uint32_t ck = (uint32_t)(ks >> 3);
            uint32_t a[4][4], b[4][4];
#pragma unroll
            for (int mi = 0; mi < 4; mi++)
                ldsm_x4(a[mi][0], a[mi][1], a[mi][2], a[mi][3],
                        stA + perA[mi] + (((ck + cA) ^ xorA[mi]) << 4));
#pragma unroll
            for (int bi = 0; bi < 4; bi++)
                ldsm_x4(b[bi][0], b[bi][1], b[bi][2], b[bi][3],
                        stB + perB[bi] + (((ck + cB) ^ xorB[bi]) << 4));
#pragma unroll
            for (int ni = 0; ni < 8; ni++) {
                uint32_t b0 = b[ni >> 1][(ni & 1) * 2];
                uint32_t b1 = b[ni >> 1][(ni & 1) * 2 + 1];
#pragma unroll
                for (int mi = 0; mi < 4; mi++)
                    mma_f16(acc[mi][ni], a[mi], b0, b1);
            }
        }
    }

    // epilogue: store unweighted output rows as fp16 (weights applied in combine)
    int gr = lane >> 2;
#pragma unroll
    for (int mi = 0; mi < 4; mi++) {
        int rl = m0 + wm * 64 + mi * 16 + gr;
        __half* y0 = g_Yh + ((size_t)e * CAP + rl) * DD + n0 + wn * 64;
        __half* y1 = y0 + (size_t)8 * DD;
#pragma unroll
        for (int ni = 0; ni < 8; ni++) {
            int c = ni * 8 + tg * 2;
            *(__half2*)(y0 + c) = __floats2half2_rn(acc[mi][ni][0], acc[mi][ni][1]);
            *(__half2*)(y1 + c) = __floats2half2_rn(acc[mi][ni][2], acc[mi][ni][3]);
        }
    }
}

// ---------------------------------------------------------------------------
// combine: out[t] = x[t] + w0*Y[e0,p0] + w1*Y[e1,p1]; coalesced, no atomics.
// ---------------------------------------------------------------------------
__global__ void __launch_bounds__(256) k_combine(const float* __restrict__ x,
                                                 float* __restrict__ out) {
    int warp = threadIdx.x >> 5, lane = threadIdx.x & 31;
    int t = blockIdx.x * 8 + warp;
    int e0 = g_tidx[t * 2], e1 = g_tidx[t * 2 + 1];
    int p0 = g_pos[t * 2], p1 = g_pos[t * 2 + 1];
    float w0 = g_tw[t * 2], w1 = g_tw[t * 2 + 1];
    const __half2* y0 = (const __half2*)(g_Yh + ((size_t)e0 * CAP + p0) * DD);
    const __half2* y1 = (const __half2*)(g_Yh + ((size_t)e1 * CAP + p1) * DD);
    const float4* xr = (const float4*)(x + (size_t)t * DD);
    float4* o = (float4*)(out + (size_t)t * DD);
#pragma unroll 4
    for (int k = lane; k < DD / 4; k += 32) {
        float4 xv = xr[k];
        float2 a0 = __half22float2(y0[2 * k]);
        float2 a1 = __half22float2(y0[2 * k + 1]);
        float2 b0 = __half22float2(y1[2 * k]);
        float2 b1 = __half22float2(y1[2 * k + 1]);
        float4 r;
        r.x = xv.x + w0 * a0.x + w1 * b0.x;
        r.y = xv.y + w0 * a0.y + w1 * b0.y;
        r.z = xv.z + w0 * a1.x + w1 * b1.x;
        r.w = xv.w + w0 * a1.y + w1 * b1.y;
        o[k] = r;
    }
}

// ---------------------------------------------------------------------------
extern "C" void kernel_launch(void* const* d_in, const int* in_sizes, int n_in,
                              void* d_out, int out_size) {
    (void)in_sizes; (void)n_in; (void)out_size;
    const float* x  = (const float*)d_in[0];
    const float* Wg = (const float*)d_in[1];
    const float* W1 = (const float*)d_in[2];
    const float* W3 = (const float*)d_in[3];
    const float* W2 = (const float*)d_in[4];
    float* out = (float*)d_out;

    cudaFuncSetAttribute(k_gemm1, cudaFuncAttributeMaxDynamicSharedMemorySize, SMEM_DYN);
    cudaFuncSetAttribute(k_gemm2, cudaFuncAttributeMaxDynamicSharedMemorySize, SMEM_DYN);
    cudaFuncSetAttribute(k_gate,  cudaFuncAttributeMaxDynamicSharedMemorySize, GATE_SMEM);

    k_convert<<<dim3((WELEMS / 4 + 255) / 256, 3), 256>>>(W1, W3, W2);
    k_init<<<(EE * CAP + 255) / 256, 256>>>();
    k_gate<<<TT / 8, 256, GATE_SMEM>>>(x, Wg);
    dim3 g1(CAP / 128, HH / 64, EE);
    k_gemm1<<<g1, 128, SMEM_DYN>>>();
    dim3 g2(CAP / 128, DD / 128, EE);
    k_gemm2<<<g2, 128, SMEM_DYN>>>();
    k_combine<<<TT / 8, 256>>>(x, out);
}

// round 15
// speedup vs baseline: 1.0266x; 1.0266x over previous
#include <cuda_runtime.h>
#include <cuda_fp16.h>
#include <cstdint>

// Problem dims
#define DD 2048
#define HH 1408
#define EE 8
#define TT 4096
#define CAP 4096
#define WELEMS (EE * HH * DD)

#define BK 64                     // halfs per stage (128B rows)
#define NS1 (DD / BK)             // 32
#define NS2 (HH / BK)             // 22
#define STAGE_B 32768             // 256 rows x 128 bytes
#define OFF_B 16384               // B region byte offset within stage
#define SMEM_DYN (512 + 3 * STAGE_B)   // 98816 -> 2 CTAs/SM
#define GATE_SMEM (EE * DD * 4)        // 65536

// ---- global scratch (no allocs allowed) ----
__device__ int    g_count[EE];
__device__ int    g_tokens[EE * CAP];   // expert slot -> token
__device__ int    g_tidx[TT * 2];       // token -> expert
__device__ int    g_pos[TT * 2];        // token -> slot within expert
__device__ float  g_tw[TT * 2];         // token -> combine weight
__device__ __half g_W1h[WELEMS];
__device__ __half g_W3h[WELEMS];
__device__ __half g_W2h[WELEMS];
__device__ __half g_xh[(size_t)TT * DD];
__device__ __half g_Gh[(size_t)EE * CAP * HH];
__device__ __half g_Yh[(size_t)EE * CAP * DD];  // unweighted expert outputs

// ---------------------------------------------------------------------------
__device__ __forceinline__ uint32_t smem_u32(const void* p) {
    uint32_t a;
    asm("{ .reg .u64 t; cvta.to.shared.u64 t, %1; cvt.u32.u64 %0, t; }" : "=r"(a) : "l"(p));
    return a;
}
#define CP16(dst, src) \
    asm volatile("cp.async.cg.shared.global [%0], [%1], 16;" :: "r"(dst), "l"(src) : "memory")
#define CP_COMMIT() asm volatile("cp.async.commit_group;" ::: "memory")
#define CP_WAIT1()  asm volatile("cp.async.wait_group 1;" ::: "memory")

// XOR-swizzled byte offset within a 128B-row tile region
__device__ __forceinline__ uint32_t swadr(int row, int chunk, int tg) {
    return (uint32_t)(row * 128 + ((chunk ^ (row & 7)) << 4) + tg * 4);
}

__device__ __forceinline__ void ldsm_x4(uint32_t& r0, uint32_t& r1,
                                        uint32_t& r2, uint32_t& r3, uint32_t addr) {
    asm volatile("ldmatrix.sync.aligned.m8n8.x4.shared.b16 {%0,%1,%2,%3}, [%4];"
                 : "=r"(r0), "=r"(r1), "=r"(r2), "=r"(r3) : "r"(addr));
}

__device__ __forceinline__ void mma_f16(float* c, const uint32_t* a,
                                        uint32_t b0, uint32_t b1) {
    asm volatile(
        "mma.sync.aligned.m16n8k16.row.col.f32.f16.f16.f32 "
        "{%0,%1,%2,%3},{%4,%5,%6,%7},{%8,%9},{%0,%1,%2,%3};"
        : "+f"(c[0]), "+f"(c[1]), "+f"(c[2]), "+f"(c[3])
        : "r"(a[0]), "r"(a[1]), "r"(a[2]), "r"(a[3]), "r"(b0), "r"(b1));
}
__device__ __forceinline__ float silu_f(float v) { return v / (1.0f + expf(-v)); }

// ---------------------------------------------------------------------------
__global__ void k_init() {
    int i = blockIdx.x * blockDim.x + threadIdx.x;
    if (i < EE * CAP) g_tokens[i] = 0;
    if (i < EE) g_count[i] = 0;
}

// streaming fp32 -> fp16 weight conversion (blockIdx.y selects tensor)
__global__ void __launch_bounds__(256) k_convert(const float* __restrict__ W1,
                                                 const float* __restrict__ W3,
                                                 const float* __restrict__ W2) {
    size_t i = ((size_t)blockIdx.x * blockDim.x + threadIdx.x) * 4;
    if (i >= WELEMS) return;
    const float* src;
    __half* dst;
    if (blockIdx.y == 0)      { src = W1; dst = g_W1h; }
    else if (blockIdx.y == 1) { src = W3; dst = g_W3h; }
    else                      { src = W2; dst = g_W2h; }
    float4 v = *(const float4*)(src + i);
    *(__half2*)(dst + i)     = __floats2half2_rn(v.x, v.y);
    *(__half2*)(dst + i + 2) = __floats2half2_rn(v.z, v.w);
}

// gating + routing fused: Wg staged in SMEM once per block (8 tokens/block,
// one warp per token). Writes x_h (fp16 copy); lane 0 routes via atomics.
__global__ void __launch_bounds__(256) k_gate(const float* __restrict__ x,
                                              const float* __restrict__ Wg) {
    extern __shared__ __align__(16) float swg[];   // [EE * DD]
    int tid = threadIdx.x;
    for (int i = tid; i < EE * DD / 4; i += 256)
        ((float4*)swg)[i] = ((const float4*)Wg)[i];
    __syncthreads();

    int warp = tid >> 5, lane = tid & 31;
    int t = blockIdx.x * 8 + warp;
    float a[EE];
#pragma unroll
    for (int e = 0; e < EE; e++) a[e] = 0.0f;
    const float4* xr = (const float4*)(x + (size_t)t * DD);
    const float4* wg = (const float4*)swg;
    __half2* xh = (__half2*)(g_xh + (size_t)t * DD);
#pragma unroll 4
    for (int k = lane; k < DD / 4; k += 32) {
        float4 xv = xr[k];
        xh[2 * k]     = __floats2half2_rn(xv.x, xv.y);
        xh[2 * k + 1] = __floats2half2_rn(xv.z, xv.w);
#pragma unroll
        for (int e = 0; e < EE; e++) {
            float4 wv = wg[e * (DD / 4) + k];
            a[e] += xv.x * wv.x + xv.y * wv.y + xv.z * wv.z + xv.w * wv.w;
        }
    }
#pragma unroll
    for (int off = 16; off; off >>= 1) {
#pragma unroll
        for (int e = 0; e < EE; e++) a[e] += __shfl_xor_sync(0xffffffffu, a[e], off);
    }
    if (lane == 0) {
        float m = a[0];
#pragma unroll
        for (int e = 1; e < EE; e++) m = fmaxf(m, a[e]);
        float s = 0.0f;
#pragma unroll
        for (int e = 0; e < EE; e++) s += expf(a[e] - m);
        int i1 = 0;
#pragma unroll
        for (int e = 1; e < EE; e++) if (a[e] > a[i1]) i1 = e;
        int i2 = (i1 == 0) ? 1 : 0;
#pragma unroll
        for (int e = 0; e < EE; e++) if (e != i1 && a[e] > a[i2]) i2 = e;
        int p1 = atomicAdd(&g_count[i1], 1);
        int p2 = atomicAdd(&g_count[i2], 1);
        g_tokens[i1 * CAP + p1] = t;
        g_tokens[i2 * CAP + p2] = t;
        g_tidx[t * 2 + 0] = i1; g_pos[t * 2 + 0] = p1;
        g_tw[t * 2 + 0] = expf(a[i1] - m) / s;
        g_tidx[t * 2 + 1] = i2; g_pos[t * 2 + 1] = p2;
        g_tw[t * 2 + 1] = expf(a[i2] - m) / s;
    }
}

// ---------------------------------------------------------------------------
// gemm1: block 128M x 128N fp16 HMMA.16816. 8 warps (4M x 2N), warp tile
// 32x64 -> 4 warps/SMSP for latency hiding; stage stays 32KB so 2 CTAs/SM.
// BK=64, XOR-swizzled SMEM, 3-stage cp.async, ldmatrix loads.
// B rows interleave W1/W3 in 32-row groups -> silu warp-local (ni vs ni+4).
// ---------------------------------------------------------------------------
__global__ void __launch_bounds__(256, 2) k_gemm1() {
    int e = blockIdx.z;
    int cnt = g_count[e];
    int m0 = blockIdx.x * 128;
    if (m0 >= cnt) return;
    int n0 = blockIdx.y * 64;   // 64 H-columns per block

    extern __shared__ __align__(16) char smem[];
    int* srow = (int*)smem;
    uint32_t sb = smem_u32(smem);
    int tid = threadIdx.x, w = tid >> 5, lane = tid & 31, tg = lane & 3;
    int wm = w >> 1, wn = w & 1;

    if (tid < 128) srow[tid] = g_tokens[e * CAP + m0 + tid] * DD;
    __syncthreads();

    // ldmatrix per-lane address components (A: 2 matrices, B: 4 matrices)
    uint32_t perA[2], xorA[2];
    int cA = (lane >> 4) & 1;
#pragma unroll
    for (int mi = 0; mi < 2; mi++) {
        int rowA = wm * 32 + mi * 16 + (lane & 7) + ((lane >> 3) & 1) * 8;
        perA[mi] = (uint32_t)(rowA * 128);
        xorA[mi] = (uint32_t)(rowA & 7);
    }
    uint32_t perB[4], xorB[4];
    int cB = (lane >> 3) & 1;
#pragma unroll
    for (int bi = 0; bi < 4; bi++) {
        int rowB = wn * 64 + (2 * bi + ((lane >> 4) & 1)) * 8 + (lane & 7);
        perB[bi] = (uint32_t)(rowB * 128);
        xorB[bi] = (uint32_t)(rowB & 7);
    }

    const __half* w1b = g_W1h + ((size_t)e * HH + n0) * DD;
    const __half* w3b = g_W3h + ((size_t)e * HH + n0) * DD;

    auto issue = [&](int s) {
        if (s < NS1) {
            int k0 = s * BK;
            uint32_t bs = sb + 512 + (s % 3) * STAGE_B;
#pragma unroll
            for (int i = 0; i < 4; i++) {
                int u = tid + i * 256, row = u >> 3, c8 = u & 7;
                CP16(bs + swadr(row, c8, 0), g_xh + srow[row] + k0 + c8 * 8);
            }
#pragma unroll
            for (int i = 0; i < 4; i++) {
                int u = tid + i * 256, row = u >> 3, c8 = u & 7;
                int colh = (row >> 6) * 32 + (row & 31);
                const __half* src = ((row & 32) ? w3b : w1b) + (size_t)colh * DD;
                CP16(bs + OFF_B + swadr(row, c8, 0), src + k0 + c8 * 8);
            }
        }
        CP_COMMIT();
    };

    float acc[2][8][4];
#pragma unroll
    for (int mi = 0; mi < 2; mi++)
#pragma unroll
        for (int ni = 0; ni < 8; ni++)
#pragma unroll
            for (int q = 0; q < 4; q++) acc[mi][ni][q] = 0.0f;

    issue(0);
    issue(1);
    for (int s = 0; s < NS1; s++) {
        CP_WAIT1();
        __syncthreads();
        issue(s + 2);
        uint32_t stA = sb + 512 + (s % 3) * STAGE_B;
        uint32_t stB = stA + OFF_B;
#pragma unroll
        for (int ks = 0; ks < 64; ks += 16) {
            uint32_t ck = (uint32_t)(ks >> 3);
            uint32_t a[2][4], b[4][4];
#pragma unroll
            for (int mi = 0; mi < 2; mi++)
                ldsm_x4(a[mi][0], a[mi][1], a[mi][2], a[mi][3],
                        stA + perA[mi] + (((ck + cA) ^ xorA[mi]) << 4));
#pragma unroll
            for (int bi = 0; bi < 4; bi++)
                ldsm_x4(b[bi][0], b[bi][1], b[bi][2], b[bi][3],
                        stB + perB[bi] + (((ck + cB) ^ xorB[bi]) << 4));
#pragma unroll
            for (int ni = 0; ni < 8; ni++) {
                uint32_t b0 = b[ni >> 1][(ni & 1) * 2];
                uint32_t b1 = b[ni >> 1][(ni & 1) * 2 + 1];
#pragma unroll
                for (int mi = 0; mi < 2; mi++)
                    mma_f16(acc[mi][ni], a[mi], b0, b1);
            }
        }
    }

    // epilogue: silu pairing warp-local (ni = W1, ni+4 = W3, same H column)
    int gr = lane >> 2;
#pragma unroll
    for (int mi = 0; mi < 2; mi++) {
        int r = m0 + wm * 32 + mi * 16 + gr;
        __half* gp = g_Gh + ((size_t)e * CAP + r) * HH + n0 + wn * 32;
#pragma unroll
        for (int ni = 0; ni < 4; ni++) {
            int c = ni * 8 + tg * 2;
            float g0 = silu_f(acc[mi][ni][0]) * acc[mi][ni + 4][0];
            float g1 = silu_f(acc[mi][ni][1]) * acc[mi][ni + 4][1];
            float g2 = silu_f(acc[mi][ni][2]) * acc[mi][ni + 4][2];
            float g3 = silu_f(acc[mi][ni][3]) * acc[mi][ni + 4][3];
            *(__half2*)(gp + c) = __floats2half2_rn(g0, g1);
            *(__half2*)(gp + (size_t)8 * HH + c) = __floats2half2_rn(g2, g3);
        }
    }
}

// ---------------------------------------------------------------------------
// gemm2: block 128M x 128N (d-cols), 8 warps (4M x 2N), warp tile 32x64,
// K over H; stores unweighted expert outputs as fp16 into g_Yh.
// ---------------------------------------------------------------------------
__global__ void __launch_bounds__(256, 2) k_gemm2() {
    int e = blockIdx.z;
    int cnt = g_count[e];
    int m0 = blockIdx.x * 128;
    if (m0 >= cnt) return;
    int n0 = blockIdx.y * 128;

    extern __shared__ __align__(16) char smem[];
    uint32_t sb = smem_u32(smem);
    int tid = threadIdx.x, w = tid >> 5, lane = tid & 31, tg = lane & 3;
    int wm = w >> 1, wn = w & 1;

    uint32_t perA[2], xorA[2];
    int cA = (lane >> 4) & 1;
#pragma unroll
    for (int mi = 0; mi < 2; mi++) {
        int rowA = wm * 32 + mi * 16 + (lane & 7) + ((lane >> 3) & 1) * 8;
        perA[mi] = (uint32_t)(rowA * 128);
        xorA[mi] = (uint32_t)(rowA & 7);
    }
    uint32_t perB[4], xorB[4];
    int cB = (lane >> 3) & 1;
#pragma unroll
    for (int bi = 0; bi < 4; bi++) {
        int rowB = wn * 64 + (2 * bi + ((lane >> 4) & 1)) * 8 + (lane & 7);
        perB[bi] = (uint32_t)(rowB * 128);
        xorB[bi] = (uint32_t)(rowB & 7);
    }

    const __half* ab  = g_Gh + ((size_t)e * CAP + m0) * HH;
    const __half* w2b = g_W2h + ((size_t)e * DD + n0) * HH;

    auto issue = [&](int s) {
        if (s < NS2) {
            int k0 = s * BK;
            uint32_t bs = sb + 512 + (s % 3) * STAGE_B;
#pragma unroll
            for (int i = 0; i < 4; i++) {
                int u = tid + i * 256, row = u >> 3, c8 = u & 7;
                CP16(bs + swadr(row, c8, 0), ab + (size_t)row * HH + k0 + c8 * 8);
            }
#pragma unroll
            for (int i = 0; i < 4; i++) {
                int u = tid + i * 256, row = u >> 3, c8 = u & 7;
                CP16(bs + OFF_B + swadr(row, c8, 0), w2b + (size_t)row * HH + k0 + c8 * 8);
            }
        }
        CP_COMMIT();
    };

    float acc[2][8][4];
#pragma unroll
    for (int mi = 0; mi < 2; mi++)
#pragma unroll
        for (int ni = 0; ni < 8; ni++)
#pragma unroll
            for (int q = 0; q < 4; q++) acc[mi][ni][q] = 0.0f;

    issue(0);
    issue(1);
    for (int s = 0; s < NS2; s++) {
        CP_WAIT1();
        __syncthreads();
        issue(s + 2);
        uint32_t stA = sb + 512 + (s % 3) * STAGE_B;
        uint32_t stB = stA + OFF_B;
#pragma unroll
        for (int ks = 0; ks < 64; ks += 16) {
            uint32_t ck = (uint32_t)(ks >> 3);
            uint32_t a[2][4], b[4][4];
#pragma unroll
            for (int mi = 0; mi < 2; mi++)
                ldsm_x4(a[mi][0], a[mi][1], a[mi][2], a[mi][3],
                        stA + perA[mi] + (((ck + cA) ^ xorA[mi]) << 4));
#pragma unroll
            for (int bi = 0; bi < 4; bi++)
                ldsm_x4(b[bi][0], b[bi][1], b[bi][2], b[bi][3],
                        stB + perB[bi] + (((ck + cB) ^ xorB[bi]) << 4));
#pragma unroll
            for (int ni = 0; ni < 8; ni++) {
                uint32_t b0 = b[ni >> 1][(ni & 1) * 2];
                uint32_t b1 = b[ni >> 1][(ni & 1) * 2 + 1];
#pragma unroll
                for (int mi = 0; mi < 2; mi++)
                    mma_f16(acc[mi][ni], a[mi], b0, b1);
            }
        }
    }

    // epilogue: store unweighted output rows as fp16 (weights applied in combine)
    int gr = lane >> 2;
#pragma unroll
    for (int mi = 0; mi < 2; mi++) {
        int rl = m0 + wm * 32 + mi * 16 + gr;
        __half* y0 = g_Yh + ((size_t)e * CAP + rl) * DD + n0 + wn * 64;
        __half* y1 = y0 + (size_t)8 * DD;
#pragma unroll
        for (int ni = 0; ni < 8; ni++) {
            int c = ni * 8 + tg * 2;
            *(__half2*)(y0 + c) = __floats2half2_rn(acc[mi][ni][0], acc[mi][ni][1]);
            *(__half2*)(y1 + c) = __floats2half2_rn(acc[mi][ni][2], acc[mi][ni][3]);
        }
    }
}

// ---------------------------------------------------------------------------
// combine: out[t] = x[t] + w0*Y[e0,p0] + w1*Y[e1,p1]; coalesced, no atomics.
// ---------------------------------------------------------------------------
__global__ void __launch_bounds__(256) k_combine(const float* __restrict__ x,
                                                 float* __restrict__ out) {
    int warp = threadIdx.x >> 5, lane = threadIdx.x & 31;
    int t = blockIdx.x * 8 + warp;
    int e0 = g_tidx[t * 2], e1 = g_tidx[t * 2 + 1];
    int p0 = g_pos[t * 2], p1 = g_pos[t * 2 + 1];
    float w0 = g_tw[t * 2], w1 = g_tw[t * 2 + 1];
    const __half2* y0 = (const __half2*)(g_Yh + ((size_t)e0 * CAP + p0) * DD);
    const __half2* y1 = (const __half2*)(g_Yh + ((size_t)e1 * CAP + p1) * DD);
    const float4* xr = (const float4*)(x + (size_t)t * DD);
    float4* o = (float4*)(out + (size_t)t * DD);
#pragma unroll 4
    for (int k = lane; k < DD / 4; k += 32) {
        float4 xv = xr[k];
        float2 a0 = __half22float2(y0[2 * k]);
        float2 a1 = __half22float2(y0[2 * k + 1]);
        float2 b0 = __half22float2(y1[2 * k]);
        float2 b1 = __half22float2(y1[2 * k + 1]);
        float4 r;
        r.x = xv.x + w0 * a0.x + w1 * b0.x;
        r.y = xv.y + w0 * a0.y + w1 * b0.y;
        r.z = xv.z + w0 * a1.x + w1 * b1.x;
        r.w = xv.w + w0 * a1.y + w1 * b1.y;
        o[k] = r;
    }
}

// ---------------------------------------------------------------------------
extern "C" void kernel_launch(void* const* d_in, const int* in_sizes, int n_in,
                              void* d_out, int out_size) {
    (void)in_sizes; (void)n_in; (void)out_size;
    const float* x  = (const float*)d_in[0];
    const float* Wg = (const float*)d_in[1];
    const float* W1 = (const float*)d_in[2];
    const float* W3 = (const float*)d_in[3];
    const float* W2 = (const float*)d_in[4];
    float* out = (float*)d_out;

    cudaFuncSetAttribute(k_gemm1, cudaFuncAttributeMaxDynamicSharedMemorySize, SMEM_DYN);
    cudaFuncSetAttribute(k_gemm2, cudaFuncAttributeMaxDynamicSharedMemorySize, SMEM_DYN);
    cudaFuncSetAttribute(k_gate,  cudaFuncAttributeMaxDynamicSharedMemorySize, GATE_SMEM);

    k_convert<<<dim3((WELEMS / 4 + 255) / 256, 3), 256>>>(W1, W3, W2);
    k_init<<<(EE * CAP + 255) / 256, 256>>>();
    k_gate<<<TT / 8, 256, GATE_SMEM>>>(x, Wg);
    dim3 g1(CAP / 128, HH / 64, EE);
    k_gemm1<<<g1, 256, SMEM_DYN>>>();
    dim3 g2(CAP / 128, DD / 128, EE);
    k_gemm2<<<g2, 256, SMEM_DYN>>>();
    k_combine<<<TT / 8, 256>>>(x, out);
}

// round 17
// speedup vs baseline: 1.0332x; 1.0064x over previous
#include <cuda_runtime.h>
#include <cuda_fp16.h>
#include <cstdint>

// Problem dims
#define DD 2048
#define HH 1408
#define EE 8
#define TT 4096
#define CAP 4096
#define WELEMS (EE * HH * DD)

#define BK 64                     // halfs per stage (128B rows)
#define NS1 (DD / BK)             // 32
#define NS2 (HH / BK)             // 22
#define NT1 (HH / 64)             // 22 N-tiles per M-block (gemm1)
#define NT2 (DD / 128)            // 16 N-tiles per M-block (gemm2)
#define STAGE_B 32768             // 256 rows x 128 bytes
#define OFF_B 16384               // B region byte offset within stage
#define SMEM_DYN (1024 + 3 * STAGE_B)  // 99328 -> 2 CTAs/SM
#define GATE_SMEM (EE * DD * 4)        // 65536
#define NCTA 296                       // persistent grid (2 per SM)

// ---- global scratch (no allocs allowed) ----
__device__ int    g_count[EE];
__device__ int    g_w1, g_w2;           // work-stealing counters
__device__ int    g_tokens[EE * CAP];   // expert slot -> token
__device__ int    g_tidx[TT * 2];       // token -> expert
__device__ int    g_pos[TT * 2];        // token -> slot within expert
__device__ float  g_tw[TT * 2];         // token -> combine weight
__device__ __half g_W1h[WELEMS];
__device__ __half g_W3h[WELEMS];
__device__ __half g_W2h[WELEMS];
__device__ __half g_xh[(size_t)TT * DD];
__device__ __half g_Gh[(size_t)EE * CAP * HH];
__device__ __half g_Yh[(size_t)EE * CAP * DD];  // unweighted expert outputs

// ---------------------------------------------------------------------------
__device__ __forceinline__ uint32_t smem_u32(const void* p) {
    uint32_t a;
    asm("{ .reg .u64 t; cvta.to.shared.u64 t, %1; cvt.u32.u64 %0, t; }" : "=r"(a) : "l"(p));
    return a;
}
#define CP16(dst, src) \
    asm volatile("cp.async.cg.shared.global [%0], [%1], 16;" :: "r"(dst), "l"(src) : "memory")
#define CP_COMMIT() asm volatile("cp.async.commit_group;" ::: "memory")
#define CP_WAIT1()  asm volatile("cp.async.wait_group 1;" ::: "memory")

// XOR-swizzled byte offset within a 128B-row tile region
__device__ __forceinline__ uint32_t swadr(int row, int chunk, int tg) {
    return (uint32_t)(row * 128 + ((chunk ^ (row & 7)) << 4) + tg * 4);
}

__device__ __forceinline__ void ldsm_x4(uint32_t& r0, uint32_t& r1,
                                        uint32_t& r2, uint32_t& r3, uint32_t addr) {
    asm volatile("ldmatrix.sync.aligned.m8n8.x4.shared.b16 {%0,%1,%2,%3}, [%4];"
                 : "=r"(r0), "=r"(r1), "=r"(r2), "=r"(r3) : "r"(addr));
}

__device__ __forceinline__ void mma_f16(float* c, const uint32_t* a,
                                        uint32_t b0, uint32_t b1) {
    asm volatile(
        "mma.sync.aligned.m16n8k16.row.col.f32.f16.f16.f32 "
        "{%0,%1,%2,%3},{%4,%5,%6,%7},{%8,%9},{%0,%1,%2,%3};"
        : "+f"(c[0]), "+f"(c[1]), "+f"(c[2]), "+f"(c[3])
        : "r"(a[0]), "r"(a[1]), "r"(a[2]), "r"(a[3]), "r"(b0), "r"(b1));
}
__device__ __forceinline__ float silu_f(float v) { return v / (1.0f + expf(-v)); }

// ---------------------------------------------------------------------------
// convert + init fused: fp32 -> fp16 weights (blockIdx.y selects tensor);
// y==0 slice also resets routing state and work counters.
__global__ void __launch_bounds__(256) k_convert(const float* __restrict__ W1,
                                                 const float* __restrict__ W3,
                                                 const float* __restrict__ W2) {
    size_t gid = (size_t)blockIdx.x * blockDim.x + threadIdx.x;
    if (blockIdx.y == 0) {
        if (gid < EE * CAP) g_tokens[gid] = 0;
        if (gid < EE) g_count[gid] = 0;
        if (gid == 0) { g_w1 = 0; g_w2 = 0; }
    }
    size_t i = gid * 4;
    if (i >= WELEMS) return;
    const float* src;
    __half* dst;
    if (blockIdx.y == 0)      { src = W1; dst = g_W1h; }
    else if (blockIdx.y == 1) { src = W3; dst = g_W3h; }
    else                      { src = W2; dst = g_W2h; }
    float4 v = *(const float4*)(src + i);
    *(__half2*)(dst + i)     = __floats2half2_rn(v.x, v.y);
    *(__half2*)(dst + i + 2) = __floats2half2_rn(v.z, v.w);
}

// gating + routing fused: Wg staged in SMEM once per block (8 tokens/block,
// one warp per token). Writes x_h (fp16 copy); lane 0 routes via atomics.
__global__ void __launch_bounds__(256) k_gate(const float* __restrict__ x,
                                              const float* __restrict__ Wg) {
    extern __shared__ __align__(16) float swg[];   // [EE * DD]
    int tid = threadIdx.x;
    for (int i = tid; i < EE * DD / 4; i += 256)
        ((float4*)swg)[i] = ((const float4*)Wg)[i];
    __syncthreads();

    int warp = tid >> 5, lane = tid & 31;
    int t = blockIdx.x * 8 + warp;
    float a[EE];
#pragma unroll
    for (int e = 0; e < EE; e++) a[e] = 0.0f;
    const float4* xr = (const float4*)(x + (size_t)t * DD);
    const float4* wg = (const float4*)swg;
    __half2* xh = (__half2*)(g_xh + (size_t)t * DD);
#pragma unroll 4
    for (int k = lane; k < DD / 4; k += 32) {
        float4 xv = xr[k];
        xh[2 * k]     = __floats2half2_rn(xv.x, xv.y);
        xh[2 * k + 1] = __floats2half2_rn(xv.z, xv.w);
#pragma unroll
        for (int e = 0; e < EE; e++) {
            float4 wv = wg[e * (DD / 4) + k];
            a[e] += xv.x * wv.x + xv.y * wv.y + xv.z * wv.z + xv.w * wv.w;
        }
    }
#pragma unroll
    for (int off = 16; off; off >>= 1) {
#pragma unroll
        for (int e = 0; e < EE; e++) a[e] += __shfl_xor_sync(0xffffffffu, a[e], off);
    }
    if (lane == 0) {
        float m = a[0];
#pragma unroll
        for (int e = 1; e < EE; e++) m = fmaxf(m, a[e]);
        float s = 0.0f;
#pragma unroll
        for (int e = 0; e < EE; e++) s += expf(a[e] - m);
        int i1 = 0;
#pragma unroll
        for (int e = 1; e < EE; e++) if (a[e] > a[i1]) i1 = e;
        int i2 = (i1 == 0) ? 1 : 0;
#pragma unroll
        for (int e = 0; e < EE; e++) if (e != i1 && a[e] > a[i2]) i2 = e;
        int p1 = atomicAdd(&g_count[i1], 1);
        int p2 = atomicAdd(&g_count[i2], 1);
        g_tokens[i1 * CAP + p1] = t;
        g_tokens[i2 * CAP + p2] = t;
        g_tidx[t * 2 + 0] = i1; g_pos[t * 2 + 0] = p1;
        g_tw[t * 2 + 0] = expf(a[i1] - m) / s;
        g_tidx[t * 2 + 1] = i2; g_pos[t * 2 + 1] = p2;
        g_tw[t * 2 + 1] = expf(a[i2] - m) / s;
    }
}

// ---------------------------------------------------------------------------
// gemm1: persistent work-stealing CTAs. Tile = 128M x 64N(H) fp16 HMMA,
// 8 warps (4M x 2N), warp tile 32x64, BK=64, XOR-swizzled SMEM, 3-stage
// cp.async, ldmatrix loads, 2 CTAs/SM. B rows interleave W1/W3 in 32-row
// groups -> silu warp-local (ni vs ni+4).
// ---------------------------------------------------------------------------
__global__ void __launch_bounds__(256, 2) k_gemm1() {
    extern __shared__ __align__(16) char smem[];
    int* srow = (int*)smem;                 // [0,512)
    int* swork = (int*)(smem + 512);        // [512,516)
    int* scum = (int*)(smem + 516);         // [516,552)  cum tiles per expert
    uint32_t sb = smem_u32(smem);
    int tid = threadIdx.x, w = tid >> 5, lane = tid & 31, tg = lane & 3;
    int wm = w >> 1, wn = w & 1;

    if (tid == 0) {
        int t = 0;
        scum[0] = 0;
#pragma unroll
        for (int ee = 0; ee < EE; ee++) {
            t += ((g_count[ee] + 127) >> 7) * NT1;
            scum[ee + 1] = t;
        }
    }

    // ldmatrix per-lane address components (A: 2 matrices, B: 4 matrices)
    uint32_t perA[2], xorA[2];
    int cA = (lane >> 4) & 1;
#pragma unroll
    for (int mi = 0; mi < 2; mi++) {
        int rowA = wm * 32 + mi * 16 + (lane & 7) + ((lane >> 3) & 1) * 8;
        perA[mi] = (uint32_t)(rowA * 128);
        xorA[mi] = (uint32_t)(rowA & 7);
    }
    uint32_t perB[4], xorB[4];
    int cB = (lane >> 3) & 1;
#pragma unroll
    for (int bi = 0; bi < 4; bi++) {
        int rowB = wn * 64 + (2 * bi + ((lane >> 4) & 1)) * 8 + (lane & 7);
        perB[bi] = (uint32_t)(rowB * 128);
        xorB[bi] = (uint32_t)(rowB & 7);
    }

    for (;;) {
        __syncthreads();                      // protect swork/srow/stage reuse
        if (tid == 0) *swork = atomicAdd(&g_w1, 1);
        __syncthreads();
        int idx = *swork;
        if (idx >= scum[EE]) return;
        int e = 0;
#pragma unroll
        for (int ee = 1; ee < EE; ee++) if (idx >= scum[ee]) e = ee;
        int rem = idx - scum[e];
        int m0 = (rem / NT1) * 128;
        int n0 = (rem % NT1) * 64;

        if (tid < 128) srow[tid] = g_tokens[e * CAP + m0 + tid] * DD;
        __syncthreads();

        const __half* w1b = g_W1h + ((size_t)e * HH + n0) * DD;
        const __half* w3b = g_W3h + ((size_t)e * HH + n0) * DD;

        auto issue = [&](int s) {
            if (s < NS1) {
                int k0 = s * BK;
                uint32_t bs = sb + 1024 + (s % 3) * STAGE_B;
#pragma unroll
                for (int i = 0; i < 4; i++) {
                    int u = tid + i * 256, row = u >> 3, c8 = u & 7;
                    CP16(bs + swadr(row, c8, 0), g_xh + srow[row] + k0 + c8 * 8);
                }
#pragma unroll
                for (int i = 0; i < 4; i++) {
                    int u = tid + i * 256, row = u >> 3, c8 = u & 7;
                    int colh = (row >> 6) * 32 + (row & 31);
                    const __half* src = ((row & 32) ? w3b : w1b) + (size_t)colh * DD;
                    CP16(bs + OFF_B + swadr(row, c8, 0), src + k0 + c8 * 8);
                }
            }
            CP_COMMIT();
        };

        float acc[2][8][4];
#pragma unroll
        for (int mi = 0; mi < 2; mi++)
#pragma unroll
            for (int ni = 0; ni < 8; ni++)
#pragma unroll
                for (int q = 0; q < 4; q++) acc[mi][ni][q] = 0.0f;

        issue(0);
        issue(1);
        for (int s = 0; s < NS1; s++) {
            CP_WAIT1();
            __syncthreads();
            issue(s + 2);
            uint32_t stA = sb + 1024 + (s % 3) * STAGE_B;
            uint32_t stB = stA + OFF_B;
#pragma unroll
            for (int ks = 0; ks < 64; ks += 16) {
                uint32_t ck = (uint32_t)(ks >> 3);
                uint32_t a[2][4], b[4][4];
#pragma unroll
                for (int mi = 0; mi < 2; mi++)
                    ldsm_x4(a[mi][0], a[mi][1], a[mi][2], a[mi][3],
                            stA + perA[mi] + (((ck + cA) ^ xorA[mi]) << 4));
#pragma unroll
                for (int bi = 0; bi < 4; bi++)
                    ldsm_x4(b[bi][0], b[bi][1], b[bi][2], b[bi][3],
                            stB + perB[bi] + (((ck + cB) ^ xorB[bi]) << 4));
#pragma unroll
                for (int ni = 0; ni < 8; ni++) {
                    uint32_t b0 = b[ni >> 1][(ni & 1) * 2];
                    uint32_t b1 = b[ni >> 1][(ni & 1) * 2 + 1];
#pragma unroll
                    for (int mi = 0; mi < 2; mi++)
                        mma_f16(acc[mi][ni], a[mi], b0, b1);
                }
            }
        }

        // epilogue: silu pairing warp-local (ni = W1, ni+4 = W3, same H col)
        int gr = lane >> 2;
#pragma unroll
        for (int mi = 0; mi < 2; mi++) {
            int r = m0 + wm * 32 + mi * 16 + gr;
            __half* gp = g_Gh + ((size_t)e * CAP + r) * HH + n0 + wn * 32;
#pragma unroll
            for (int ni = 0; ni < 4; ni++) {
                int c = ni * 8 + tg * 2;
                float g0 = silu_f(acc[mi][ni][0]) * acc[mi][ni + 4][0];
                float g1 = silu_f(acc[mi][ni][1]) * acc[mi][ni + 4][1];
                float g2 = silu_f(acc[mi][ni][2]) * acc[mi][ni + 4][2];
                float g3 = silu_f(acc[mi][ni][3]) * acc[mi][ni + 4][3];
                *(__half2*)(gp + c) = __floats2half2_rn(g0, g1);
                *(__half2*)(gp + (size_t)8 * HH + c) = __floats2half2_rn(g2, g3);
            }
        }
    }
}

// ---------------------------------------------------------------------------
// gemm2: persistent work-stealing CTAs. Tile = 128M x 128N(d), 8 warps
// (4M x 2N), warp tile 32x64, K over H; stores unweighted outputs to g_Yh.
// ---------------------------------------------------------------------------
__global__ void __launch_bounds__(256, 2) k_gemm2() {
    extern __shared__ __align__(16) char smem[];
    int* swork = (int*)(smem + 512);
    int* scum = (int*)(smem + 516);
    uint32_t sb = smem_u32(smem);
    int tid = threadIdx.x, w = tid >> 5, lane = tid & 31, tg = lane & 3;
    int wm = w >> 1, wn = w & 1;

    if (tid == 0) {
        int t = 0;
        scum[0] = 0;
#pragma unroll
        for (int ee = 0; ee < EE; ee++) {
            t += ((g_count[ee] + 127) >> 7) * NT2;
            scum[ee + 1] = t;
        }
    }

    uint32_t perA[2], xorA[2];
    int cA = (lane >> 4) & 1;
#pragma unroll
    for (int mi = 0; mi < 2; mi++) {
        int rowA = wm * 32 + mi * 16 + (lane & 7) + ((lane >> 3) & 1) * 8;
        perA[mi] = (uint32_t)(rowA * 128);
        xorA[mi] = (uint32_t)(rowA & 7);
    }
    uint32_t perB[4], xorB[4];
    int cB = (lane >> 3) & 1;
#pragma unroll
    for (int bi = 0; bi < 4; bi++) {
        int rowB = wn * 64 + (2 * bi + ((lane >> 4) & 1)) * 8 + (lane & 7);
        perB[bi] = (uint32_t)(rowB * 128);
        xorB[bi] = (uint32_t)(rowB & 7);
    }

    for (;;) {
        __syncthreads();
        if (tid == 0) *swork = atomicAdd(&g_w2, 1);
        __syncthreads();
        int idx = *swork;
        if (idx >= scum[EE]) return;
        int e = 0;
#pragma unroll
        for (int ee = 1; ee < EE; ee++) if (idx >= scum[ee]) e = ee;
        int rem = idx - scum[e];
        int m0 = (rem / NT2) * 128;
        int n0 = (rem % NT2) * 128;

        const __half* ab  = g_Gh + ((size_t)e * CAP + m0) * HH;
        const __half* w2b = g_W2h + ((size_t)e * DD + n0) * HH;

        auto issue = [&](int s) {
            if (s < NS2) {
                int k0 = s * BK;
                uint32_t bs = sb + 1024 + (s % 3) * STAGE_B;
#pragma unroll
                for (int i = 0; i < 4; i++) {
                    int u = tid + i * 256, row = u >> 3, c8 = u & 7;
                    CP16(bs + swadr(row, c8, 0), ab + (size_t)row * HH + k0 + c8 * 8);
                }
#pragma unroll
                for (int i = 0; i < 4; i++) {
                    int u = tid + i * 256, row = u >> 3, c8 = u & 7;
                    CP16(bs + OFF_B + swadr(row, c8, 0), w2b + (size_t)row * HH + k0 + c8 * 8);
                }
            }
            CP_COMMIT();
        };

        float acc[2][8][4];
#pragma unroll
        for (int mi = 0; mi < 2; mi++)
#pragma unroll
            for (int ni = 0; ni < 8; ni++)
#pragma unroll
                for (int q = 0; q < 4; q++) acc[mi][ni][q] = 0.0f;

        issue(0);
        issue(1);
        for (int s = 0; s < NS2; s++) {
            CP_WAIT1();
            __syncthreads();
            issue(s + 2);
            uint32_t stA = sb + 1024 + (s % 3) * STAGE_B;
            uint32_t stB = stA + OFF_B;
#pragma unroll
            for (int ks = 0; ks < 64; ks += 16) {
                uint32_t ck = (uint32_t)(ks >> 3);
                uint32_t a[2][4], b[4][4];
#pragma unroll
                for (int mi = 0; mi < 2; mi++)
                    ldsm_x4(a[mi][0], a[mi][1], a[mi][2], a[mi][3],
                            stA + perA[mi] + (((ck + cA) ^ xorA[mi]) << 4));
#pragma unroll
                for (int bi = 0; bi < 4; bi++)
                    ldsm_x4(b[bi][0], b[bi][1], b[bi][2], b[bi][3],
                            stB + perB[bi] + (((ck + cB) ^ xorB[bi]) << 4));
#pragma unroll
                for (int ni = 0; ni < 8; ni++) {
                    uint32_t b0 = b[ni >> 1][(ni & 1) * 2];
                    uint32_t b1 = b[ni >> 1][(ni & 1) * 2 + 1];
#pragma unroll
                    for (int mi = 0; mi < 2; mi++)
                        mma_f16(acc[mi][ni], a[mi], b0, b1);
                }
            }
        }

        // epilogue: store unweighted output rows as fp16
        int gr = lane >> 2;
#pragma unroll
        for (int mi = 0; mi < 2; mi++) {
            int rl = m0 + wm * 32 + mi * 16 + gr;
            __half* y0 = g_Yh + ((size_t)e * CAP + rl) * DD + n0 + wn * 64;
            __half* y1 = y0 + (size_t)8 * DD;
#pragma unroll
            for (int ni = 0; ni < 8; ni++) {
                int c = ni * 8 + tg * 2;
                *(__half2*)(y0 + c) = __floats2half2_rn(acc[mi][ni][0], acc[mi][ni][1]);
                *(__half2*)(y1 + c) = __floats2half2_rn(acc[mi][ni][2], acc[mi][ni][3]);
            }
        }
    }
}

// ---------------------------------------------------------------------------
// combine: out[t] = x[t] + w0*Y[e0,p0] + w1*Y[e1,p1]; coalesced, no atomics.
// ---------------------------------------------------------------------------
__global__ void __launch_bounds__(256) k_combine(const float* __restrict__ x,
                                                 float* __restrict__ out) {
    int warp = threadIdx.x >> 5, lane = threadIdx.x & 31;
    int t = blockIdx.x * 8 + warp;
    int e0 = g_tidx[t * 2], e1 = g_tidx[t * 2 + 1];
    int p0 = g_pos[t * 2], p1 = g_pos[t * 2 + 1];
    float w0 = g_tw[t * 2], w1 = g_tw[t * 2 + 1];
    const __half2* y0 = (const __half2*)(g_Yh + ((size_t)e0 * CAP + p0) * DD);
    const __half2* y1 = (const __half2*)(g_Yh + ((size_t)e1 * CAP + p1) * DD);
    const float4* xr = (const float4*)(x + (size_t)t * DD);
    float4* o = (float4*)(out + (size_t)t * DD);
#pragma unroll 4
    for (int k = lane; k < DD / 4; k += 32) {
        float4 xv = xr[k];
        float2 a0 = __half22float2(y0[2 * k]);
        float2 a1 = __half22float2(y0[2 * k + 1]);
        float2 b0 = __half22float2(y1[2 * k]);
        float2 b1 = __half22float2(y1[2 * k + 1]);
        float4 r;
        r.x = xv.x + w0 * a0.x + w1 * b0.x;
        r.y = xv.y + w0 * a0.y + w1 * b0.y;
        r.z = xv.z + w0 * a1.x + w1 * b1.x;
        r.w = xv.w + w0 * a1.y + w1 * b1.y;
        o[k] = r;
    }
}

// ---------------------------------------------------------------------------
extern "C" void kernel_launch(void* const* d_in, const int* in_sizes, int n_in,
                              void* d_out, int out_size) {
    (void)in_sizes; (void)n_in; (void)out_size;
    const float* x  = (const float*)d_in[0];
    const float* Wg = (const float*)d_in[1];
    const float* W1 = (const float*)d_in[2];
    const float* W3 = (const float*)d_in[3];
    const float* W2 = (const float*)d_in[4];
    float* out = (float*)d_out;

    cudaFuncSetAttribute(k_gemm1, cudaFuncAttributeMaxDynamicSharedMemorySize, SMEM_DYN);
    cudaFuncSetAttribute(k_gemm2, cudaFuncAttributeMaxDynamicSharedMemorySize, SMEM_DYN);
    cudaFuncSetAttribute(k_gate,  cudaFuncAttributeMaxDynamicSharedMemorySize, GATE_SMEM);

    k_convert<<<dim3((WELEMS / 4 + 255) / 256, 3), 256>>>(W1, W3, W2);
    k_gate<<<TT / 8, 256, GATE_SMEM>>>(x, Wg);
    k_gemm1<<<NCTA, 256, SMEM_DYN>>>();
    k_gemm2<<<NCTA, 256, SMEM_DYN>>>();
    k_combine<<<TT / 8, 256>>>(x, out);
}